// round 17
// baseline (speedup 1.0000x reference)
#include <cuda_runtime.h>
#include <cuda_fp16.h>
#include <cstdint>
#include <math.h>

#define BB 64
#define TT 512
#define EE 256
#define HH 768
#define G4 3072
#define VV 5000

#define NCTA 128          // persistent CTAs, 6 hidden units each
#define UPC  6
#define NKC  48           // K=768 / 16 (fp16 mma k16 chunks)
#define WFRAG_U4_PER_CTA (NKC*3*32)     // 4608 uint4 per CTA (W_hh fp16 hi/lo packed)
#define HFRAG_E 49152                   // 64*768 fp16 elements per slot
#define NVT 625                         // 5000/8 vocab n-tiles (125 CTAs x 5)
#define FCF_U2 (NVT*NKC*32)             // 960000 uint2

// ---------------- device scratch ----------------
__device__ float g_proj[(size_t)VV * G4];                 // embed@W_ih^T + biases
__device__ __align__(16) uint4 g_wfrag[(size_t)NCTA * WFRAG_U4_PER_CTA];
__device__ __align__(16) __half g_hfrag[(size_t)513 * HFRAG_E]; // h A-fragments per t; slot 512 = zeros
__device__ __align__(16) uint2 g_fcfrag[(size_t)FCF_U2]; // fc_w B-fragments fp16
__device__ unsigned g_flag[NCTA * 32];                    // arrival flags, 128B-spaced

__device__ __forceinline__ float to_tf32(float x){
    uint32_t u; asm("cvt.rna.tf32.f32 %0, %1;" : "=r"(u) : "f"(x));
    return __uint_as_float(u);
}
__device__ __forceinline__ uint32_t fu(float x){ return __float_as_uint(x); }
__device__ __forceinline__ void mma_tf32(float* c, const uint32_t* a, const uint32_t* b){
    asm volatile("mma.sync.aligned.m16n8k8.row.col.f32.tf32.tf32.f32 "
        "{%0,%1,%2,%3}, {%4,%5,%6,%7}, {%8,%9}, {%0,%1,%2,%3};"
        : "+f"(c[0]), "+f"(c[1]), "+f"(c[2]), "+f"(c[3])
        : "r"(a[0]), "r"(a[1]), "r"(a[2]), "r"(a[3]), "r"(b[0]), "r"(b[1]));
}
__device__ __forceinline__ void mma_fp16(float* c, const uint32_t* a, uint32_t b0, uint32_t b1){
    asm volatile("mma.sync.aligned.m16n8k16.row.col.f32.f16.f16.f32 "
        "{%0,%1,%2,%3}, {%4,%5,%6,%7}, {%8,%9}, {%0,%1,%2,%3};"
        : "+f"(c[0]), "+f"(c[1]), "+f"(c[2]), "+f"(c[3])
        : "r"(a[0]), "r"(a[1]), "r"(a[2]), "r"(a[3]), "r"(b0), "r"(b1));
}
__device__ __forceinline__ uint32_t pack_h2(float lo_elem, float hi_elem){
    return (uint32_t)__half_as_ushort(__float2half_rn(lo_elem))
         | ((uint32_t)__half_as_ushort(__float2half_rn(hi_elem)) << 16);
}
// fast sigmoid/tanh via MUFU (err ~2^-21)
__device__ __forceinline__ float fsig(float x){
    float e; asm("ex2.approx.ftz.f32 %0, %1;" : "=f"(e) : "f"(-1.4426950408889634f * x));
    float r; asm("rcp.approx.ftz.f32 %0, %1;" : "=f"(r) : "f"(1.f + e));
    return r;
}
__device__ __forceinline__ float ftanh(float x){ return 2.f * fsig(2.f * x) - 1.f; }

// ---------------- prep ----------------
__global__ void k_prep(const float* __restrict__ Whh, const float* __restrict__ fcw){
    int i = blockIdx.x * blockDim.x + threadIdx.x;
    if (i < HFRAG_E) g_hfrag[(size_t)512 * HFRAG_E + i] = __float2half(0.f);
    if (i < NCTA * 32) g_flag[i] = 0u;
    if (i < FCF_U2){
        int vt = i / 1536, r = i % 1536, kc = r / 32, lane = r & 31;
        int col = vt * 8 + (lane >> 2);
        const float* wr = fcw + (size_t)col * HH + kc * 16 + 2 * (lane & 3);
        uint2 v;
        v.x = pack_h2(wr[0], wr[1]);
        v.y = pack_h2(wr[8], wr[9]);
        g_fcfrag[i] = v;
    }
    if (i < NCTA * WFRAG_U4_PER_CTA){
        int cta = i / WFRAG_U4_PER_CTA;
        int j   = i % WFRAG_U4_PER_CTA;
        int kc  = j / 96, j2 = j % 96, nt = j2 >> 5, lane = j2 & 31;
        int lr = lane >> 2, lc = lane & 3;
        int n_local = nt * 8 + lr;
        int u = n_local >> 2, gate = n_local & 3;
        int grow = gate * HH + cta * UPC + u;
        const float* wr = Whh + (size_t)grow * HH + kc * 16;
        float w00 = wr[2*lc],     w01 = wr[2*lc + 1];
        float w10 = wr[2*lc + 8], w11 = wr[2*lc + 9];
        float h00 = __half2float(__float2half_rn(w00));
        float h01 = __half2float(__float2half_rn(w01));
        float h10 = __half2float(__float2half_rn(w10));
        float h11 = __half2float(__float2half_rn(w11));
        uint4 v;
        v.x = pack_h2(h00, h01);
        v.y = pack_h2(h10, h11);
        v.z = pack_h2(w00 - h00, w01 - h01);
        v.w = pack_h2(w10 - h10, w11 - h11);
        g_wfrag[i] = v;
    }
}

// ---------------- tf32 GEMM (proj): C = A[M,K] @ B[N,K]^T + bias1 + bias2 ----------------
__global__ __launch_bounds__(256) void k_gemm(
    const float* __restrict__ A, const float* __restrict__ Bm, float* __restrict__ C,
    int M, int N, int K, const float* __restrict__ bias1, const float* __restrict__ bias2)
{
    __shared__ float As[128][36];
    __shared__ float Bs[128][36];
    const int tid = threadIdx.x;
    const int w = tid >> 5, lane = tid & 31;
    const int lr = lane >> 2, lc = lane & 3;
    const int m0 = blockIdx.y * 128, n0 = blockIdx.x * 128;
    const int wm = (w >> 1) * 32, wn = (w & 1) * 64;
    float acc[2][8][4];
    #pragma unroll
    for (int i = 0; i < 2; i++)
        #pragma unroll
        for (int j = 0; j < 8; j++)
            #pragma unroll
            for (int q = 0; q < 4; q++) acc[i][j][q] = 0.f;
    float4 pa[4], pb[4];
    #pragma unroll
    for (int i = 0; i < 4; i++){
        int f = tid + i * 256; int r = f >> 3, cf = (f & 7) * 4;
        pa[i] = make_float4(0.f,0.f,0.f,0.f);
        if (m0 + r < M) pa[i] = *(const float4*)(A + (size_t)(m0 + r) * K + cf);
        pb[i] = make_float4(0.f,0.f,0.f,0.f);
        if (n0 + r < N) pb[i] = *(const float4*)(Bm + (size_t)(n0 + r) * K + cf);
    }
    for (int k0 = 0; k0 < K; k0 += 32){
        #pragma unroll
        for (int i = 0; i < 4; i++){
            int f = tid + i * 256; int r = f >> 3, cf = (f & 7) * 4;
            float4 ta = pa[i], tb = pb[i];
            As[r][cf+0] = to_tf32(ta.x); As[r][cf+1] = to_tf32(ta.y);
            As[r][cf+2] = to_tf32(ta.z); As[r][cf+3] = to_tf32(ta.w);
            Bs[r][cf+0] = to_tf32(tb.x); Bs[r][cf+1] = to_tf32(tb.y);
            Bs[r][cf+2] = to_tf32(tb.z); Bs[r][cf+3] = to_tf32(tb.w);
        }
        __syncthreads();
        int k1 = k0 + 32;
        if (k1 < K){
            #pragma unroll
            for (int i = 0; i < 4; i++){
                int f = tid + i * 256; int r = f >> 3, cf = (f & 7) * 4;
                pa[i] = make_float4(0.f,0.f,0.f,0.f);
                if (m0 + r < M) pa[i] = *(const float4*)(A + (size_t)(m0 + r) * K + k1 + cf);
                pb[i] = make_float4(0.f,0.f,0.f,0.f);
                if (n0 + r < N) pb[i] = *(const float4*)(Bm + (size_t)(n0 + r) * K + k1 + cf);
            }
        }
        #pragma unroll
        for (int kk = 0; kk < 32; kk += 8){
            uint32_t af[2][4], bf[8][2];
            #pragma unroll
            for (int mt = 0; mt < 2; mt++){
                int rb = wm + mt * 16;
                af[mt][0] = fu(As[rb + lr][kk + lc]);
                af[mt][1] = fu(As[rb + 8 + lr][kk + lc]);
                af[mt][2] = fu(As[rb + lr][kk + lc + 4]);
                af[mt][3] = fu(As[rb + 8 + lr][kk + lc + 4]);
            }
            #pragma unroll
            for (int nt = 0; nt < 8; nt++){
                int cb = wn + nt * 8;
                bf[nt][0] = fu(Bs[cb + lr][kk + lc]);
                bf[nt][1] = fu(Bs[cb + lr][kk + lc + 4]);
            }
            #pragma unroll
            for (int mt = 0; mt < 2; mt++)
                #pragma unroll
                for (int nt = 0; nt < 8; nt++)
                    mma_tf32(acc[mt][nt], af[mt], bf[nt]);
        }
        __syncthreads();
    }
    #pragma unroll
    for (int mt = 0; mt < 2; mt++)
        #pragma unroll
        for (int nt = 0; nt < 8; nt++){
            #pragma unroll
            for (int q = 0; q < 4; q++){
                int row = m0 + wm + mt * 16 + lr + (q >> 1) * 8;
                int col = n0 + wn + nt * 8 + lc * 2 + (q & 1);
                if (row < M && col < N){
                    float v = acc[mt][nt][q];
                    if (bias1) v += bias1[col];
                    if (bias2) v += bias2[col];
                    C[(size_t)row * N + col] = v;
                }
            }
        }
}

// ---------------- persistent: gate warps 0-3 (recurrence, in-reg pointwise) + FC warps 4-7 ----------------
__global__ __launch_bounds__(256, 1) void k_persist(const int* __restrict__ x,
                                                    float* __restrict__ out,
                                                    const float* __restrict__ fcb)
{
    extern __shared__ char smraw[];
    uint4* Bsm = (uint4*)smraw;                         // 73728 B
    uint2* Fsm = (uint2*)(smraw + WFRAG_U4_PER_CTA*16); // 61440 B
    const int tid  = threadIdx.x;
    const int w    = tid >> 5, lane = tid & 31;
    const int lr   = lane >> 2, lc = lane & 3, lc2 = lc * 2;
    const int cta  = blockIdx.x;
    const bool has_fc = (cta < 125);
    const bool isgate = (w < 4);
    const int wf = w & 3;

    {   // persistent weights -> smem
        const uint4* wsrc = g_wfrag + (size_t)cta * WFRAG_U4_PER_CTA;
        for (int i = tid; i < WFRAG_U4_PER_CTA; i += 256) Bsm[i] = wsrc[i];
        if (has_fc){
            const uint2* fsrc = g_fcfrag + (size_t)cta * 5 * NKC * 32;
            for (int i = tid; i < 5 * NKC * 32; i += 256) Fsm[i] = fsrc[i];
        }
    }

    // FC bias regs
    float bv[5][2];
    #pragma unroll
    for (int v = 0; v < 5; v++){
        int col = (cta * 5 + v) * 8 + lc2;
        bv[v][0] = has_fc ? fcb[col] : 0.f;
        bv[v][1] = has_fc ? fcb[col + 1] : 0.f;
    }

    // gate-thread pointwise identity: row b, units u(nt) = 2*nt + (lc>>1)
    const int pb_ = wf * 16 + lr + (lc & 1) * 8;   // batch row owned by this gate thread
    const int ub_ = lc >> 1;                        // unit offset parity
    float creg[3] = {0.f, 0.f, 0.f};
    float pv[3][4];
    if (isgate){
        int xv = __ldg(x + pb_ * TT);               // t = 0
        #pragma unroll
        for (int nt = 0; nt < 3; nt++){
            int u = 2 * nt + ub_;
            const float* pr = g_proj + (size_t)xv * G4 + (cta * UPC + u);
            #pragma unroll
            for (int g = 0; g < 4; g++) pv[nt][g] = __ldg(pr + g * HH);
        }
    }
    unsigned genreg = 0;
    __syncthreads();

    for (int t = 0; t < TT; t++){
        const uint4* Ah = (const uint4*)(g_hfrag + (size_t)((t == 0) ? 512 : (t - 1)) * HFRAG_E);

        if (isgate){
            // ---- gate GEMM ----
            float accH[3][4], accL[3][4];
            #pragma unroll
            for (int n = 0; n < 3; n++)
                #pragma unroll
                for (int q = 0; q < 4; q++){ accH[n][q] = 0.f; accL[n][q] = 0.f; }
            uint4 ahb[8];
            #pragma unroll
            for (int j = 0; j < 8; j++)
                ahb[j] = __ldg(Ah + (j * 4 + wf) * 32 + lane);
            for (int c = 0; c < 6; c++){
                #pragma unroll
                for (int j = 0; j < 8; j++){
                    int kc = c * 8 + j;
                    uint4 a4 = ahb[j];
                    if (kc + 8 < NKC)
                        ahb[j] = __ldg(Ah + ((kc + 8) * 4 + wf) * 32 + lane);
                    uint32_t ah[4] = {a4.x, a4.y, a4.z, a4.w};
                    #pragma unroll
                    for (int nt = 0; nt < 3; nt++){
                        uint4 bb = Bsm[(kc * 3 + nt) * 32 + lane];
                        mma_fp16(accH[nt], ah, bb.x, bb.y);
                        mma_fp16(accL[nt], ah, bb.z, bb.w);
                    }
                }
            }
            // ---- in-register pointwise via lane-XOR-1 gate exchange ----
            __half* hdst = g_hfrag + (size_t)t * HFRAG_E;
            #pragma unroll
            for (int nt = 0; nt < 3; nt++){
                float g0 = accH[nt][0] + accL[nt][0];
                float g1 = accH[nt][1] + accL[nt][1];
                float g2 = accH[nt][2] + accL[nt][2];
                float g3 = accH[nt][3] + accL[nt][3];
                float e0 = __shfl_xor_sync(0xffffffffu, g0, 1);
                float e1 = __shfl_xor_sync(0xffffffffu, g1, 1);
                float e2 = __shfl_xor_sync(0xffffffffu, g2, 1);
                float e3 = __shfl_xor_sync(0xffffffffu, g3, 1);
                float gi, gf, gg, go;
                if ((lc & 1) == 0){ gi = g0; gf = g1; gg = e0; go = e1; }
                else              { gi = e2; gf = e3; gg = g2; go = g3; }
                gi += pv[nt][0]; gf += pv[nt][1]; gg += pv[nt][2]; go += pv[nt][3];
                float cnew = fsig(gf) * creg[nt] + fsig(gi) * ftanh(gg);
                float hnew = fsig(go) * ftanh(cnew);
                creg[nt] = cnew;
                int ug = cta * UPC + 2 * nt + ub_;
                int kch = ug >> 4, kk = ug & 15;
                int r = pb_ & 15, wb = pb_ >> 4;
                int lane_h = (r & 7) * 4 + ((kk & 7) >> 1);
                int reg = (r >> 3) + 2 * (kk >> 3);
                int half = kk & 1;
                int elem = (((kch * 4 + wb) * 32 + lane_h) * 4 + reg) * 2 + half;
                hdst[elem] = __float2half_rn(hnew);
            }
            __threadfence();
            asm volatile("bar.sync 1, 128;" ::: "memory");   // gate warps only
            genreg += 1;
            if (tid == 0)
                asm volatile("st.release.gpu.global.u32 [%0], %1;"
                    :: "l"(&g_flag[cta * 32]), "r"(genreg) : "memory");
            // pv prefetch for t+1 (hidden in barrier window)
            if (t + 1 < TT){
                int xv = __ldg(x + pb_ * TT + t + 1);
                #pragma unroll
                for (int nt = 0; nt < 3; nt++){
                    int u = 2 * nt + ub_;
                    const float* pr = g_proj + (size_t)xv * G4 + (cta * UPC + u);
                    #pragma unroll
                    for (int g = 0; g < 4; g++) pv[nt][g] = __ldg(pr + g * HH);
                }
            }
            if (w == 0){   // warp 0 polls all 128 flags
                unsigned f0, f1, f2, f3; unsigned ok;
                do {
                    asm volatile("ld.acquire.gpu.global.u32 %0, [%1];" : "=r"(f0) : "l"(&g_flag[lane * 32]));
                    asm volatile("ld.acquire.gpu.global.u32 %0, [%1];" : "=r"(f1) : "l"(&g_flag[(lane + 32) * 32]));
                    asm volatile("ld.acquire.gpu.global.u32 %0, [%1];" : "=r"(f2) : "l"(&g_flag[(lane + 64) * 32]));
                    asm volatile("ld.acquire.gpu.global.u32 %0, [%1];" : "=r"(f3) : "l"(&g_flag[(lane + 96) * 32]));
                    ok = ((int)(f0 - genreg) >= 0) && ((int)(f1 - genreg) >= 0)
                      && ((int)(f2 - genreg) >= 0) && ((int)(f3 - genreg) >= 0);
                } while (__ballot_sync(0xffffffffu, ok) != 0xffffffffu);
            }
        } else {
            // ---- FC for t-1, fully parallel with the gate chain ----
            genreg += 1;
            if (has_fc && t > 0){
                float accF[5][4];
                #pragma unroll
                for (int n = 0; n < 5; n++)
                    #pragma unroll
                    for (int q = 0; q < 4; q++) accF[n][q] = 0.f;
                uint4 fring[8];
                #pragma unroll
                for (int j = 0; j < 8; j++)
                    fring[j] = __ldg(Ah + (j * 4 + wf) * 32 + lane);
                for (int c = 0; c < 6; c++){
                    #pragma unroll
                    for (int j = 0; j < 8; j++){
                        int kc = c * 8 + j;
                        uint4 a4 = fring[j];
                        if (kc + 8 < NKC)
                            fring[j] = __ldg(Ah + ((kc + 8) * 4 + wf) * 32 + lane);
                        uint32_t ah[4] = {a4.x, a4.y, a4.z, a4.w};
                        #pragma unroll
                        for (int v = 0; v < 5; v++){
                            uint2 f2 = Fsm[(v * NKC + kc) * 32 + lane];
                            mma_fp16(accF[v], ah, f2.x, f2.y);
                        }
                    }
                }
                int tfc = t - 1;
                #pragma unroll
                for (int v = 0; v < 5; v++){
                    int colb = (cta * 5 + v) * 8 + lc2;
                    #pragma unroll
                    for (int h = 0; h < 2; h++){
                        int b = wf * 16 + lr + h * 8;
                        float2 o = make_float2(accF[v][2*h] + bv[v][0], accF[v][2*h+1] + bv[v][1]);
                        *(float2*)(out + (size_t)(b * TT + tfc) * VV + colb) = o;
                    }
                }
            }
        }
        __syncthreads();   // joins gate (post-poll) and FC warps; publishes slot t to all
    }

    // tail: FC for t = 511 (h(511) published by the final barrier)
    if (!isgate && has_fc){
        const uint4* Ah = (const uint4*)(g_hfrag + (size_t)511 * HFRAG_E);
        float accF[5][4];
        #pragma unroll
        for (int n = 0; n < 5; n++)
            #pragma unroll
            for (int q = 0; q < 4; q++) accF[n][q] = 0.f;
        for (int kc = 0; kc < NKC; kc++){
            uint4 a4 = __ldg(Ah + (kc * 4 + wf) * 32 + lane);
            uint32_t ah[4] = {a4.x, a4.y, a4.z, a4.w};
            #pragma unroll
            for (int v = 0; v < 5; v++){
                uint2 f2 = Fsm[(v * NKC + kc) * 32 + lane];
                mma_fp16(accF[v], ah, f2.x, f2.y);
            }
        }
        #pragma unroll
        for (int v = 0; v < 5; v++){
            int colb = (cta * 5 + v) * 8 + lc2;
            #pragma unroll
            for (int h = 0; h < 2; h++){
                int b = wf * 16 + lr + h * 8;
                float2 o = make_float2(accF[v][2*h] + bv[v][0], accF[v][2*h+1] + bv[v][1]);
                *(float2*)(out + (size_t)(b * TT + 511) * VV + colb) = o;
            }
        }
    }
}

// ---------------- host launch ----------------
extern "C" void kernel_launch(void* const* d_in, const int* in_sizes, int n_in,
                              void* d_out, int out_size)
{
    const int* x = 0;
    const float *embed = 0, *W_ih = 0, *W_hh = 0, *b_ih = 0, *b_hh = 0, *fc_w = 0, *fc_b = 0;
    for (int i = 0; i < n_in; i++){
        switch (in_sizes[i]){
            case BB*TT:      x     = (const int*)  d_in[i]; break;
            case VV*EE:      embed = (const float*)d_in[i]; break;
            case G4*EE:      W_ih  = (const float*)d_in[i]; break;
            case G4*HH:      W_hh  = (const float*)d_in[i]; break;
            case G4:         if (!b_ih) b_ih = (const float*)d_in[i];
                             else        b_hh = (const float*)d_in[i]; break;
            case VV*HH:      fc_w  = (const float*)d_in[i]; break;
            case VV:         fc_b  = (const float*)d_in[i]; break;
            default: break;  // truncate_length — identity in forward pass
        }
    }
    float* out = (float*)d_out;
    float* p_proj = 0;
    cudaGetSymbolAddress((void**)&p_proj, g_proj);

    const int SMEM = WFRAG_U4_PER_CTA * 16 + 61440;   // 135168 (no gate-tile smem anymore)
    cudaFuncSetAttribute(k_persist, cudaFuncAttributeMaxDynamicSharedMemorySize, SMEM);

    // 1) prep: W_hh + fc_w fragments, zero h slot 512 + flags (replay-safe)
    {
        int n = FCF_U2;   // 960000 covers all prep ranges
        k_prep<<<(n + 255) / 256, 256>>>(W_hh, fc_w);
    }
    // 2) proj[V,4H] = embed @ W_ih^T + b_ih + b_hh  (tf32)
    {
        dim3 grid(G4 / 128, (VV + 127) / 128);
        k_gemm<<<grid, 256>>>(embed, W_ih, p_proj, VV, G4, EE, b_ih, b_hh);
    }
    // 3) persistent recurrence + parallel FC: 1 launch
    k_persist<<<NCTA, 256, SMEM>>>(x, out, fc_b);
}